// round 1
// baseline (speedup 1.0000x reference)
#include <cuda_runtime.h>

typedef unsigned long long ull;

// ---------------- scratch (__device__ globals; no allocation) ----------------
__device__ float g_z1[1024 * 64 * 1024];   // conv1 output [img][oc][y][x]  (268MB)
__device__ float g_pool[1024 * 128];       // pooled conv2 features
__device__ float g_h[1024 * 256];          // fc output (masked) [b*32+n][256]
__device__ float g_out1[1024 * 256];       // sage1 output
__device__ float g_cs[2][32 * 256];        // per-batch column sums
__device__ float g_wc1[256 * 256];         // rw - lw/31 (layer 1)
__device__ float g_wc2[128 * 256];         // rw - lw/31 (layer 2)
__device__ float g_base1[32 * 256];        // colsum@lw/31 + lb (layer 1)
__device__ float g_base2[32 * 128];        // layer 2

// ---------------- f32x2 packed helpers (Blackwell) ----------------
__device__ __forceinline__ ull pk2(float v) {
    ull r; asm("mov.b64 %0, {%1, %2};" : "=l"(r) : "f"(v), "f"(v)); return r;
}
__device__ __forceinline__ ull ffma2(ull a, ull b, ull c) {
    ull d; asm("fma.rn.f32x2 %0, %1, %2, %3;" : "=l"(d) : "l"(a), "l"(b), "l"(c)); return d;
}
__device__ __forceinline__ float2 upk(ull v) {
    float2 f; asm("mov.b64 {%0, %1}, %2;" : "=f"(f.x), "=f"(f.y) : "l"(v)); return f;
}

// ---------------- conv1 (3->64, 3x3 SAME) + ReLU ----------------
// one block per image; thread t owns 4 horizontally-adjacent pixels (row t/8, cols (t%8)*4..+3)
__global__ __launch_bounds__(256) void conv1_kernel(const float* __restrict__ x,
                                                    const float* __restrict__ w,
                                                    const float* __restrict__ bias) {
    __shared__ float sIn[3 * 1024];
    __shared__ float sW[27 * 64];   // [ic*9+kt][oc]
    __shared__ float sB[64];
    int img = blockIdx.x, tid = threadIdx.x;
    for (int j = tid; j < 3072; j += 256) sIn[j] = x[img * 3072 + j];
    for (int e = tid; e < 1728; e += 256) { int k = e >> 6, o = e & 63; sW[e] = w[o * 27 + k]; }
    if (tid < 64) sB[tid] = bias[tid];
    __syncthreads();
    int r = tid >> 3, x0 = (tid & 7) << 2;
    for (int oc0 = 0; oc0 < 64; oc0 += 16) {
        float acc[4][16];
#pragma unroll
        for (int p = 0; p < 4; p++)
#pragma unroll
            for (int o = 0; o < 16; o++) acc[p][o] = sB[oc0 + o];
#pragma unroll
        for (int ic = 0; ic < 3; ic++) {
#pragma unroll
            for (int ky = 0; ky < 3; ky++) {
                int yy = r + ky - 1;
                float iv[6];
                if ((unsigned)yy < 32u) {
                    const float* row = sIn + ic * 1024 + yy * 32;
#pragma unroll
                    for (int j = 0; j < 6; j++) {
                        int xx = x0 - 1 + j;
                        iv[j] = ((unsigned)xx < 32u) ? row[xx] : 0.f;
                    }
                } else {
#pragma unroll
                    for (int j = 0; j < 6; j++) iv[j] = 0.f;
                }
#pragma unroll
                for (int kx = 0; kx < 3; kx++) {
                    const float* wp = sW + (ic * 9 + ky * 3 + kx) * 64 + oc0;
                    float wv[16];
#pragma unroll
                    for (int o = 0; o < 16; o++) wv[o] = wp[o];
#pragma unroll
                    for (int p = 0; p < 4; p++) {
                        float v = iv[p + kx];
#pragma unroll
                        for (int o = 0; o < 16; o++) acc[p][o] = fmaf(v, wv[o], acc[p][o]);
                    }
                }
            }
        }
        float* dst = g_z1 + (size_t)img * 65536 + (size_t)oc0 * 1024 + tid * 4;
#pragma unroll
        for (int o = 0; o < 16; o++) {
            float4 v = make_float4(fmaxf(acc[0][o], 0.f), fmaxf(acc[1][o], 0.f),
                                   fmaxf(acc[2][o], 0.f), fmaxf(acc[3][o], 0.f));
            *reinterpret_cast<float4*>(dst + o * 1024) = v;
        }
    }
}

// ---------------- conv2 (64->128) + ReLU + global mean pool, fused ----------------
// grid (1024 images, 8 oc-groups of 16); f32x2 packed FMA on oc pairs.
__global__ __launch_bounds__(256) void conv2_pool_kernel(const float* __restrict__ w,
                                                         const float* __restrict__ bias) {
    extern __shared__ float smem[];
    float* sIn  = smem;            // 16 ic * 1024 px = 16384 floats
    float* sW   = smem + 16384;    // 144 * 16 floats  (pairs of adjacent oc -> ull)
    float* sRed = sW + 2304;       // 8 warps * 16
    int img = blockIdx.x;
    int oc0 = blockIdx.y * 16;
    int tid = threadIdx.x;
    int r = tid >> 3, x0 = (tid & 7) << 2;
    ull z = pk2(0.f);
    ull acc[4][8];
#pragma unroll
    for (int p = 0; p < 4; p++)
#pragma unroll
        for (int j = 0; j < 8; j++) acc[p][j] = z;

    for (int ic0 = 0; ic0 < 64; ic0 += 16) {
        __syncthreads();
        const float4* src = reinterpret_cast<const float4*>(g_z1 + (size_t)img * 65536 + (size_t)ic0 * 1024);
        float4* d4 = reinterpret_cast<float4*>(sIn);
#pragma unroll
        for (int j = 0; j < 16; j++) d4[tid + j * 256] = src[tid + j * 256];
        for (int e = tid; e < 2304; e += 256) {
            int k = e >> 4, o = e & 15, ic_l = k / 9, kt = k % 9;
            sW[e] = w[(oc0 + o) * 576 + (ic0 + ic_l) * 9 + kt];
        }
        __syncthreads();
        for (int ic = 0; ic < 16; ic++) {
            const float* in = sIn + ic * 1024;
#pragma unroll
            for (int ky = 0; ky < 3; ky++) {
                int yy = r + ky - 1;
                ull iv2[6];
                if ((unsigned)yy < 32u) {
                    const float* row = in + yy * 32;
#pragma unroll
                    for (int j = 0; j < 6; j++) {
                        int xx = x0 - 1 + j;
                        iv2[j] = pk2(((unsigned)xx < 32u) ? row[xx] : 0.f);
                    }
                } else {
#pragma unroll
                    for (int j = 0; j < 6; j++) iv2[j] = z;
                }
#pragma unroll
                for (int kx = 0; kx < 3; kx++) {
                    const ull* wp = reinterpret_cast<const ull*>(sW + (ic * 9 + ky * 3 + kx) * 16);
                    ull wr[8];
#pragma unroll
                    for (int j = 0; j < 8; j++) wr[j] = wp[j];
#pragma unroll
                    for (int p = 0; p < 4; p++) {
                        ull v = iv2[p + kx];
#pragma unroll
                        for (int j = 0; j < 8; j++) acc[p][j] = ffma2(v, wr[j], acc[p][j]);
                    }
                }
            }
        }
    }
    // bias + relu + local pool over the thread's 4 pixels
    float s[16];
#pragma unroll
    for (int j = 0; j < 8; j++) {
        float b0 = bias[oc0 + 2 * j], b1 = bias[oc0 + 2 * j + 1];
        float s0 = 0.f, s1 = 0.f;
#pragma unroll
        for (int p = 0; p < 4; p++) {
            float2 f = upk(acc[p][j]);
            s0 += fmaxf(f.x + b0, 0.f);
            s1 += fmaxf(f.y + b1, 0.f);
        }
        s[2 * j] = s0; s[2 * j + 1] = s1;
    }
#pragma unroll
    for (int off = 16; off > 0; off >>= 1)
#pragma unroll
        for (int o = 0; o < 16; o++) s[o] += __shfl_xor_sync(0xffffffffu, s[o], off);
    int lane = tid & 31, warp = tid >> 5;
    __syncthreads();
    if (lane == 0) {
#pragma unroll
        for (int o = 0; o < 16; o++) sRed[warp * 16 + o] = s[o];
    }
    __syncthreads();
    if (tid < 16) {
        float t = 0.f;
#pragma unroll
        for (int wv = 0; wv < 8; wv++) t += sRed[wv * 16 + tid];
        g_pool[img * 128 + oc0 + tid] = t * (1.f / 1024.f);
    }
}

// ---------------- FC 128->256 + mask ----------------
__global__ __launch_bounds__(256) void fc_kernel(const float* __restrict__ fw,
                                                 const float* __restrict__ fb,
                                                 const float* __restrict__ mask) {
    __shared__ float sP[128];
    int i = blockIdx.x, o = threadIdx.x;
    if (o < 128) sP[o] = g_pool[i * 128 + o];
    __syncthreads();
    float acc = fb[o];
    const float4* w4 = reinterpret_cast<const float4*>(fw + o * 128);
    const float4* p4 = reinterpret_cast<const float4*>(sP);
    float s = 0.f;
#pragma unroll 8
    for (int k = 0; k < 32; k++) {
        float4 wv = w4[k], pv = p4[k];
        s = fmaf(wv.x, pv.x, s); s = fmaf(wv.y, pv.y, s);
        s = fmaf(wv.z, pv.z, s); s = fmaf(wv.w, pv.w, s);
    }
    g_h[i * 256 + o] = (acc + s) * mask[i];
}

// ---------------- per-batch column sums over nodes ----------------
__global__ void colsum_kernel(int layer) {
    int b = blockIdx.x, d = threadIdx.x;
    const float* src = layer ? g_out1 : g_h;
    float s = 0.f;
#pragma unroll 8
    for (int n = 0; n < 32; n++) s += src[(b * 32 + n) * 256 + d];
    g_cs[layer][b * 256 + d] = s;
}

// ---------------- combined weight: rw - lw/31 ----------------
__global__ void wcomb_kernel(const float* __restrict__ lw, const float* __restrict__ rw, int layer) {
    int e = blockIdx.x * 256 + threadIdx.x;
    float* dst = layer ? g_wc2 : g_wc1;
    dst[e] = rw[e] - lw[e] * (1.f / 31.f);
}

// ---------------- base: lb + colsum@lw/31 ----------------
__global__ void base_kernel(const float* __restrict__ lw, const float* __restrict__ lb, int layer) {
    int b = blockIdx.x, o = threadIdx.x;
    const float* csr = g_cs[layer] + b * 256;
    const float* wr = lw + o * 256;
    float s = 0.f;
#pragma unroll 8
    for (int d = 0; d < 256; d++) s = fmaf(csr[d], wr[d], s);
    float* dst = layer ? g_base2 : g_base1;
    dst[b * (int)blockDim.x + o] = lb[o] + s * (1.f / 31.f);
}

// ---------------- node GEMM: out = base + h @ wcomb^T (+ relu for layer 1) ----------------
__global__ void sage_gemm_kernel(int layer, float* __restrict__ dout) {
    __shared__ float sH[256];
    int i = blockIdx.x, o = threadIdx.x, b = i >> 5;
    int O = blockDim.x;
    const float* hin = layer ? g_out1 : g_h;
    const float* wc  = layer ? g_wc2 : g_wc1;
    const float* base = layer ? g_base2 : g_base1;
    for (int j = o; j < 256; j += O) sH[j] = hin[i * 256 + j];
    __syncthreads();
    float acc = base[b * O + o];
    const float4* w4 = reinterpret_cast<const float4*>(wc + o * 256);
    const float4* h4 = reinterpret_cast<const float4*>(sH);
    float s = 0.f;
#pragma unroll 8
    for (int k = 0; k < 64; k++) {
        float4 wv = w4[k], hv = h4[k];
        s = fmaf(wv.x, hv.x, s); s = fmaf(wv.y, hv.y, s);
        s = fmaf(wv.z, hv.z, s); s = fmaf(wv.w, hv.w, s);
    }
    acc += s;
    if (!layer) acc = fmaxf(acc, 0.f);
    float* out = layer ? dout : g_out1;
    out[i * O + o] = acc;
}

// ---------------- launch ----------------
extern "C" void kernel_launch(void* const* d_in, const int* in_sizes, int n_in,
                              void* d_out, int out_size) {
    const float* x       = (const float*)d_in[0];
    const float* mask    = (const float*)d_in[1];
    const float* conv1_w = (const float*)d_in[2];
    const float* conv1_b = (const float*)d_in[3];
    const float* conv2_w = (const float*)d_in[4];
    const float* conv2_b = (const float*)d_in[5];
    const float* fc_w    = (const float*)d_in[6];
    const float* fc_b    = (const float*)d_in[7];
    const float* s1_lw   = (const float*)d_in[8];
    const float* s1_lb   = (const float*)d_in[9];
    const float* s1_rw   = (const float*)d_in[10];
    const float* s2_lw   = (const float*)d_in[11];
    const float* s2_lb   = (const float*)d_in[12];
    const float* s2_rw   = (const float*)d_in[13];
    float* out = (float*)d_out;

    const int SMEM2 = (16384 + 2304 + 128) * 4;  // 75264 bytes
    cudaFuncSetAttribute(conv2_pool_kernel, cudaFuncAttributeMaxDynamicSharedMemorySize, SMEM2);

    conv1_kernel<<<1024, 256>>>(x, conv1_w, conv1_b);
    conv2_pool_kernel<<<dim3(1024, 8), 256, SMEM2>>>(conv2_w, conv2_b);
    fc_kernel<<<1024, 256>>>(fc_w, fc_b, mask);

    colsum_kernel<<<32, 256>>>(0);
    wcomb_kernel<<<256, 256>>>(s1_lw, s1_rw, 0);
    base_kernel<<<32, 256>>>(s1_lw, s1_lb, 0);
    sage_gemm_kernel<<<1024, 256>>>(0, out);

    colsum_kernel<<<32, 256>>>(1);
    wcomb_kernel<<<128, 256>>>(s2_lw, s2_rw, 1);
    base_kernel<<<32, 128>>>(s2_lw, s2_lb, 1);
    sage_gemm_kernel<<<1024, 128>>>(1, out);
}